// round 9
// baseline (speedup 1.0000x reference)
#include <cuda_runtime.h>
#include <cuda_bf16.h>
#include <math.h>

#define BB 64
#define TT 512
#define SS 512
#define NC 64
#define AT 128
#define NN 128
#define G4 2048
#define KT 64

// ---------------- persistent scratch (device globals; no allocation) ----------------
__device__ __align__(256) float g_psiT[(size_t)BB * AT * TT];  // [b][a][t] 16.8 MB
__device__ __align__(256) float g_h1[BB * SS];
__device__ __align__(256) float g_h2[BB * SS];
__device__ __align__(256) float g_c1[BB * SS];
__device__ __align__(256) float g_c2[BB * SS];
__device__ __align__(256) float g_ctx[BB * SS];
__device__ __align__(256) float g_gp[2][BB * G4];              // gate partials per K-source
__device__ __align__(256) float g_bs0[G4];                     // bih0 + bhh0
__device__ __align__(256) float g_bs1[G4];                     // bih1 + bhh1

__device__ __forceinline__ float sigf(float v) { return 1.0f / (1.0f + expf(-v)); }

// ---------------- init: fused biases, ctx = h[:,0,:], zero states ----------------
__global__ void init_kernel(const float* __restrict__ h,
                            const float* __restrict__ bih0, const float* __restrict__ bhh0,
                            const float* __restrict__ bih1, const float* __restrict__ bhh1)
{
    int idx = blockIdx.x * blockDim.x + threadIdx.x;   // 0..32767
    if (idx < G4) {
        g_bs0[idx] = bih0[idx] + bhh0[idx];
        g_bs1[idx] = bih1[idx] + bhh1[idx];
    }
    if (idx < BB * SS) {
        int b = idx >> 9, d = idx & 511;
        g_ctx[idx] = h[(size_t)b * TT * SS + d];       // h[b, 0, d]
        g_h1[idx] = 0.f; g_h2[idx] = 0.f;
        g_c1[idx] = 0.f; g_c2[idx] = 0.f;
    }
}

// ---------------- psi precompute (transposed): psiT[b][a][t] = h[b,t,:].Wpsi[a,:] + bpsi[a] ----
__global__ void __launch_bounds__(128) psi_kernel(const float* __restrict__ h,
                                                  const float* __restrict__ Wpsi,
                                                  const float* __restrict__ bpsi)
{
    __shared__ float4 s_hr[16][128];                   // 16 (b,t) rows x 512 floats
    const int tid = threadIdx.x;
    const int r0 = blockIdx.x * 16;
    #pragma unroll
    for (int i = 0; i < 16; i++) {
        int f = tid + 128 * i;                         // 0..2047 float4 slots
        int r = f >> 7, c = f & 127;
        s_hr[r][c] = ((const float4*)(h + (size_t)(r0 + r) * SS))[c];
    }
    __syncthreads();
    float acc[16];
    #pragma unroll
    for (int r = 0; r < 16; r++) acc[r] = 0.f;
    const float4* wr = (const float4*)(Wpsi + (size_t)tid * SS);
    for (int k = 0; k < 128; k++) {
        float4 w = wr[k];
        #pragma unroll
        for (int r = 0; r < 16; r++) {
            float4 v = s_hr[r][k];
            acc[r] += w.x * v.x + w.y * v.y + w.z * v.z + w.w * v.w;
        }
    }
    float bp = bpsi[tid];
    #pragma unroll
    for (int r = 0; r < 16; r++) {
        int row = r0 + r;
        int b = row >> 9, t = row & 511;
        g_psiT[((size_t)b * AT + tid) * TT + t] = acc[r] + bp;
    }
}

// ---------------- LSTM gate GEMM, K-split over gridDim.y ----------------
// mode 0: (ctx . Wih0[:,64:]) | (h1 . Whh0)     mode 1: (h1 . Wih1) | (h2 . Whh1)
// grid (64, 2), block 256 = 32 rows x 8 batch-groups of 8. Writes g_gp[gy][b*2048 + r].
__global__ void __launch_bounds__(256) gemm_kernel(int mode,
                                                   const float* __restrict__ WA, int lda, int coffa,
                                                   const float* __restrict__ WB)
{
    __shared__ float sA[BB][72];   // act chunk [b][k], padded
    __shared__ float sW[32][65];   // W chunk [row][k], stride-65 => conflict-free scalar reads

    const int gy = blockIdx.y;
    const float* act;
    const float* W;
    int ldw, coff;
    if (gy == 0) { act = (mode == 0) ? g_ctx : g_h1; W = WA; ldw = lda; coff = coffa; }
    else         { act = (mode == 0) ? g_h1  : g_h2; W = WB; ldw = SS;  coff = 0;     }
    float* outp = g_gp[gy];

    const int tid = threadIdx.x;
    const int lr  = tid & 31;            // row within the 32-row group
    const int bg  = tid >> 5;            // 0..7
    const int b0  = bg * 8;
    const int r   = blockIdx.x * 32 + lr;

    float acc[8];
    #pragma unroll
    for (int i = 0; i < 8; i++) acc[i] = 0.f;

    float4 pa[4];                        // prefetch regs: act  (4 float4 / thread / chunk)
    float4 pw[2];                        // prefetch regs: W    (2 float4 / thread / chunk)

    // prefetch chunk 0
    {
        #pragma unroll
        for (int i = 0; i < 4; i++) {
            int u = tid + 256 * i;       // 0..1023
            int b = u >> 4, k4 = u & 15;
            pa[i] = *(const float4*)(act + b * SS + k4 * 4);
        }
        #pragma unroll
        for (int j = 0; j < 2; j++) {
            int v = tid + 256 * j;       // 0..511
            int rr = v >> 4, k4 = v & 15;
            pw[j] = *(const float4*)(W + (size_t)(blockIdx.x * 32 + rr) * ldw + coff + k4 * 4);
        }
    }

    for (int kc = 0; kc < SS; kc += KT) {
        // stage prefetched regs into smem
        #pragma unroll
        for (int i = 0; i < 4; i++) {
            int u = tid + 256 * i;
            int b = u >> 4, k4 = u & 15;
            *(float4*)&sA[b][k4 * 4] = pa[i];
        }
        #pragma unroll
        for (int j = 0; j < 2; j++) {
            int v = tid + 256 * j;
            int rr = v >> 4, k4 = v & 15;
            sW[rr][k4 * 4 + 0] = pw[j].x;
            sW[rr][k4 * 4 + 1] = pw[j].y;
            sW[rr][k4 * 4 + 2] = pw[j].z;
            sW[rr][k4 * 4 + 3] = pw[j].w;
        }
        __syncthreads();

        // prefetch next chunk
        if (kc + KT < SS) {
            int kn = kc + KT;
            #pragma unroll
            for (int i = 0; i < 4; i++) {
                int u = tid + 256 * i;
                int b = u >> 4, k4 = u & 15;
                pa[i] = *(const float4*)(act + b * SS + kn + k4 * 4);
            }
            #pragma unroll
            for (int j = 0; j < 2; j++) {
                int v = tid + 256 * j;
                int rr = v >> 4, k4 = v & 15;
                pw[j] = *(const float4*)(W + (size_t)(blockIdx.x * 32 + rr) * ldw + coff + kn + k4 * 4);
            }
        }

        // compute this chunk
        #pragma unroll 8
        for (int k = 0; k < KT; k += 4) {
            float w0 = sW[lr][k + 0];
            float w1 = sW[lr][k + 1];
            float w2 = sW[lr][k + 2];
            float w3 = sW[lr][k + 3];
            #pragma unroll
            for (int i = 0; i < 8; i++) {
                float4 a4 = *(const float4*)&sA[b0 + i][k];
                acc[i] += w0 * a4.x + w1 * a4.y + w2 * a4.z + w3 * a4.w;
            }
        }
        __syncthreads();
    }

    #pragma unroll
    for (int i = 0; i < 8; i++)
        outp[(size_t)(b0 + i) * G4 + r] = acc[i];
}

// ---------------- fused cell: combine partials + bias + onehot gather + LSTM gates ----------------
// grid 64 (b), 512 threads (d). mode 0 updates (h1,c1) w/ onehot; mode 1 updates (h2,c2).
__global__ void __launch_bounds__(512) cell_kernel(int mode, int step,
                                                   const int* __restrict__ x,
                                                   const float* __restrict__ Wih0)
{
    const int b = blockIdx.x, d = threadIdx.x;
    const size_t base = (size_t)b * G4;
    const float* bs = (mode == 0) ? g_bs0 : g_bs1;

    float gi = g_gp[0][base + d]        + g_gp[1][base + d]        + bs[d];
    float gf = g_gp[0][base + d + 512]  + g_gp[1][base + d + 512]  + bs[d + 512];
    float gg = g_gp[0][base + d + 1024] + g_gp[1][base + d + 1024] + bs[d + 1024];
    float go = g_gp[0][base + d + 1536] + g_gp[1][base + d + 1536] + bs[d + 1536];

    if (mode == 0) {
        int col = x[b * NN + step];
        gi += Wih0[(size_t)(d)        * 576 + col];
        gf += Wih0[(size_t)(d + 512)  * 576 + col];
        gg += Wih0[(size_t)(d + 1024) * 576 + col];
        go += Wih0[(size_t)(d + 1536) * 576 + col];
    }

    float* cbuf = (mode == 0) ? g_c1 : g_c2;
    float* hbuf = (mode == 0) ? g_h1 : g_h2;
    int idx = b * SS + d;
    float c = cbuf[idx];
    float cn = sigf(gf) * c + sigf(gi) * tanhf(gg);
    cbuf[idx] = cn;
    hbuf[idx] = sigf(go) * tanhf(cn);
}

// ---------------- fused attention + projection ----------------
// grid 64 (b), 512 threads. phi -> e -> softmax -> ctx -> p.
__global__ void __launch_bounds__(512) attn_kernel(const float* __restrict__ h,
                                                   const float* __restrict__ Wphi,
                                                   const float* __restrict__ bphi,
                                                   const float* __restrict__ Wcd,
                                                   const float* __restrict__ bcd,
                                                   float* __restrict__ out, int step)
{
    __shared__ __align__(16) float s_h2[SS];
    __shared__ __align__(16) float s_ctx[SS];
    __shared__ float s_phi[AT];
    __shared__ float s_alpha[TT];
    __shared__ float s_red[32];

    const int b = blockIdx.x, tid = threadIdx.x;
    const int lane = tid & 31, wid = tid >> 5;

    s_h2[tid] = g_h2[b * SS + tid];
    __syncthreads();

    // phi_s[a] = h2[b,:] . Wphi[a,:] + bphi[a]
    if (tid < AT) {
        const float4* wr = (const float4*)(Wphi + (size_t)tid * SS);
        const float4* hh = (const float4*)s_h2;
        float a = 0.f;
        #pragma unroll 4
        for (int k = 0; k < 128; k++) {
            float4 w = wr[k], v = hh[k];
            a += w.x * v.x + w.y * v.y + w.z * v.z + w.w * v.w;
        }
        s_phi[tid] = a + bphi[tid];
    }
    __syncthreads();

    // e[t] = phi . psiT[b][:][t]   (coalesced over t = tid)
    const float* prow = g_psiT + (size_t)b * AT * TT + tid;
    float e = 0.f;
    #pragma unroll 8
    for (int a = 0; a < AT; a++) e += s_phi[a] * prow[(size_t)a * TT];

    // block softmax over t (512)
    float m = e;
    #pragma unroll
    for (int off = 16; off; off >>= 1) m = fmaxf(m, __shfl_xor_sync(0xffffffffu, m, off));
    if (lane == 0) s_red[wid] = m;
    __syncthreads();
    if (wid == 0) {
        float v = (lane < 16) ? s_red[lane] : -1e30f;
        #pragma unroll
        for (int off = 8; off; off >>= 1) v = fmaxf(v, __shfl_xor_sync(0xffffffffu, v, off));
        if (lane == 0) s_red[0] = v;
    }
    __syncthreads();
    float M = s_red[0];
    float ex = expf(e - M);
    __syncthreads();
    float ssum = ex;
    #pragma unroll
    for (int off = 16; off; off >>= 1) ssum += __shfl_xor_sync(0xffffffffu, ssum, off);
    if (lane == 0) s_red[wid] = ssum;
    __syncthreads();
    if (wid == 0) {
        float v = (lane < 16) ? s_red[lane] : 0.f;
        #pragma unroll
        for (int off = 8; off; off >>= 1) v += __shfl_xor_sync(0xffffffffu, v, off);
        if (lane == 0) s_red[0] = v;
    }
    __syncthreads();
    s_alpha[tid] = ex / s_red[0];
    __syncthreads();

    // ctx[d] = sum_t alpha[t] * h[b,t,d]   (coalesced over d = tid)
    const float* hb = h + (size_t)b * TT * SS + tid;
    float acc = 0.f;
    #pragma unroll 8
    for (int t = 0; t < TT; t++) acc += s_alpha[t] * hb[(size_t)t * SS];
    s_ctx[tid] = acc;
    g_ctx[b * SS + tid] = acc;
    __syncthreads();

    // p[c] = concat(h2, ctx) . Wcd[c,:] + bcd[c]; 4 partial threads per class
    if (tid < 256) {
        int c = tid >> 2, part = tid & 3;
        const float4* wv = (const float4*)(Wcd + (size_t)c * 1024) + part * 64;
        const float4* src = (part < 2) ? ((const float4*)s_h2 + (part & 1) * 64)
                                       : ((const float4*)s_ctx + (part & 1) * 64);
        float p = 0.f;
        #pragma unroll 4
        for (int j = 0; j < 64; j++) {
            float4 w = wv[j], v = src[j];
            p += w.x * v.x + w.y * v.y + w.z * v.z + w.w * v.w;
        }
        p += __shfl_xor_sync(0xffffffffu, p, 1);
        p += __shfl_xor_sync(0xffffffffu, p, 2);
        if (part == 0)
            out[((size_t)b * NN + step) * NC + c] = p + bcd[c];
    }
}

// ---------------- host launcher ----------------
extern "C" void kernel_launch(void* const* d_in, const int* in_sizes, int n_in,
                              void* d_out, int out_size)
{
    const int*   x    = (const int*)  d_in[0];
    const float* h    = (const float*)d_in[1];
    const float* Wih0 = (const float*)d_in[2];
    const float* Whh0 = (const float*)d_in[3];
    const float* bih0 = (const float*)d_in[4];
    const float* bhh0 = (const float*)d_in[5];
    const float* Wih1 = (const float*)d_in[6];
    const float* Whh1 = (const float*)d_in[7];
    const float* bih1 = (const float*)d_in[8];
    const float* bhh1 = (const float*)d_in[9];
    const float* Wphi = (const float*)d_in[10];
    const float* bphi = (const float*)d_in[11];
    const float* Wpsi = (const float*)d_in[12];
    const float* bpsi = (const float*)d_in[13];
    const float* Wcd  = (const float*)d_in[14];
    const float* bcd  = (const float*)d_in[15];
    float* out = (float*)d_out;

    init_kernel<<<128, 256>>>(h, bih0, bhh0, bih1, bhh1);
    psi_kernel<<<(BB * TT) / 16, 128>>>(h, Wpsi, bpsi);

    dim3 ggrid(G4 / 32, 2);
    for (int s = 0; s < NN; s++) {
        gemm_kernel<<<ggrid, 256>>>(0, Wih0, 576, 64, Whh0);
        cell_kernel<<<BB, 512>>>(0, s, x, Wih0);
        gemm_kernel<<<ggrid, 256>>>(1, Wih1, 512, 0, Whh1);
        cell_kernel<<<BB, 512>>>(1, s, x, Wih0);
        attn_kernel<<<BB, 512>>>(h, Wphi, bphi, Wcd, bcd, out, s);
    }
}

// round 10
// speedup vs baseline: 1.0398x; 1.0398x over previous
#include <cuda_runtime.h>
#include <cuda_bf16.h>
#include <math.h>

#define BB 64
#define TT 512
#define SS 512
#define NC 64
#define AT 128
#define NN 128
#define G4 2048
#define KT 64

// ---------------- persistent scratch (device globals; no allocation) ----------------
__device__ __align__(256) float g_psiT[(size_t)BB * AT * TT];  // [b][a][t] 16.8 MB
__device__ __align__(256) float g_h1[BB * SS];
__device__ __align__(256) float g_h2[BB * SS];
__device__ __align__(256) float g_c1[BB * SS];
__device__ __align__(256) float g_c2[BB * SS];
__device__ __align__(256) float g_ctx[BB * SS];
__device__ __align__(256) float g_gp[2][BB * G4];              // gate partials per K-source
__device__ __align__(256) float g_bs0[G4];                     // bih0 + bhh0
__device__ __align__(256) float g_bs1[G4];                     // bih1 + bhh1

__device__ __forceinline__ float sigf(float v) { return 1.0f / (1.0f + expf(-v)); }

// ---------------- init: fused biases, ctx = h[:,0,:], zero states ----------------
__global__ void init_kernel(const float* __restrict__ h,
                            const float* __restrict__ bih0, const float* __restrict__ bhh0,
                            const float* __restrict__ bih1, const float* __restrict__ bhh1)
{
    int idx = blockIdx.x * blockDim.x + threadIdx.x;   // 0..32767
    if (idx < G4) {
        g_bs0[idx] = bih0[idx] + bhh0[idx];
        g_bs1[idx] = bih1[idx] + bhh1[idx];
    }
    if (idx < BB * SS) {
        int b = idx >> 9, d = idx & 511;
        g_ctx[idx] = h[(size_t)b * TT * SS + d];       // h[b, 0, d]
        g_h1[idx] = 0.f; g_h2[idx] = 0.f;
        g_c1[idx] = 0.f; g_c2[idx] = 0.f;
    }
}

// ---------------- psi precompute (transposed): psiT[b][a][t] = h[b,t,:].Wpsi[a,:] + bpsi[a] ----
__global__ void __launch_bounds__(128) psi_kernel(const float* __restrict__ h,
                                                  const float* __restrict__ Wpsi,
                                                  const float* __restrict__ bpsi)
{
    __shared__ float4 s_hr[16][128];                   // 16 (b,t) rows x 512 floats
    const int tid = threadIdx.x;
    const int r0 = blockIdx.x * 16;
    #pragma unroll
    for (int i = 0; i < 16; i++) {
        int f = tid + 128 * i;                         // 0..2047 float4 slots
        int r = f >> 7, c = f & 127;
        s_hr[r][c] = ((const float4*)(h + (size_t)(r0 + r) * SS))[c];
    }
    __syncthreads();
    float acc[16];
    #pragma unroll
    for (int r = 0; r < 16; r++) acc[r] = 0.f;
    const float4* wr = (const float4*)(Wpsi + (size_t)tid * SS);
    for (int k = 0; k < 128; k++) {
        float4 w = wr[k];
        #pragma unroll
        for (int r = 0; r < 16; r++) {
            float4 v = s_hr[r][k];
            acc[r] += w.x * v.x + w.y * v.y + w.z * v.z + w.w * v.w;
        }
    }
    float bp = bpsi[tid];
    #pragma unroll
    for (int r = 0; r < 16; r++) {
        int row = r0 + r;
        int b = row >> 9, t = row & 511;
        g_psiT[((size_t)b * AT + tid) * TT + t] = acc[r] + bp;
    }
}

// ---------------- LSTM gate GEMM, K-split over gridDim.y ----------------
// mode 0: (ctx . Wih0[:,64:]) | (h1 . Whh0)     mode 1: (h1 . Wih1) | (h2 . Whh1)
// grid (64, 2), block 256 = 32 rows x 8 batch-groups of 8. Writes g_gp[gy][b*2048 + r].
__global__ void __launch_bounds__(256) gemm_kernel(int mode,
                                                   const float* __restrict__ WA, int lda, int coffa,
                                                   const float* __restrict__ WB)
{
    __shared__ float sA[BB][72];   // act chunk [b][k], padded
    __shared__ float sW[32][65];   // W chunk [row][k], stride-65 => conflict-free scalar reads

    const int gy = blockIdx.y;
    const float* act;
    const float* W;
    int ldw, coff;
    if (gy == 0) { act = (mode == 0) ? g_ctx : g_h1; W = WA; ldw = lda; coff = coffa; }
    else         { act = (mode == 0) ? g_h1  : g_h2; W = WB; ldw = SS;  coff = 0;     }
    float* outp = g_gp[gy];

    const int tid = threadIdx.x;
    const int lr  = tid & 31;            // row within the 32-row group
    const int bg  = tid >> 5;            // 0..7
    const int b0  = bg * 8;
    const int r   = blockIdx.x * 32 + lr;

    float acc[8];
    #pragma unroll
    for (int i = 0; i < 8; i++) acc[i] = 0.f;

    float4 pa[4];                        // prefetch regs: act  (4 float4 / thread / chunk)
    float4 pw[2];                        // prefetch regs: W    (2 float4 / thread / chunk)

    // prefetch chunk 0
    {
        #pragma unroll
        for (int i = 0; i < 4; i++) {
            int u = tid + 256 * i;       // 0..1023
            int b = u >> 4, k4 = u & 15;
            pa[i] = *(const float4*)(act + b * SS + k4 * 4);
        }
        #pragma unroll
        for (int j = 0; j < 2; j++) {
            int v = tid + 256 * j;       // 0..511
            int rr = v >> 4, k4 = v & 15;
            pw[j] = *(const float4*)(W + (size_t)(blockIdx.x * 32 + rr) * ldw + coff + k4 * 4);
        }
    }

    for (int kc = 0; kc < SS; kc += KT) {
        // stage prefetched regs into smem
        #pragma unroll
        for (int i = 0; i < 4; i++) {
            int u = tid + 256 * i;
            int b = u >> 4, k4 = u & 15;
            *(float4*)&sA[b][k4 * 4] = pa[i];
        }
        #pragma unroll
        for (int j = 0; j < 2; j++) {
            int v = tid + 256 * j;
            int rr = v >> 4, k4 = v & 15;
            sW[rr][k4 * 4 + 0] = pw[j].x;
            sW[rr][k4 * 4 + 1] = pw[j].y;
            sW[rr][k4 * 4 + 2] = pw[j].z;
            sW[rr][k4 * 4 + 3] = pw[j].w;
        }
        __syncthreads();

        // prefetch next chunk
        if (kc + KT < SS) {
            int kn = kc + KT;
            #pragma unroll
            for (int i = 0; i < 4; i++) {
                int u = tid + 256 * i;
                int b = u >> 4, k4 = u & 15;
                pa[i] = *(const float4*)(act + b * SS + kn + k4 * 4);
            }
            #pragma unroll
            for (int j = 0; j < 2; j++) {
                int v = tid + 256 * j;
                int rr = v >> 4, k4 = v & 15;
                pw[j] = *(const float4*)(W + (size_t)(blockIdx.x * 32 + rr) * ldw + coff + kn + k4 * 4);
            }
        }

        // compute this chunk
        #pragma unroll 8
        for (int k = 0; k < KT; k += 4) {
            float w0 = sW[lr][k + 0];
            float w1 = sW[lr][k + 1];
            float w2 = sW[lr][k + 2];
            float w3 = sW[lr][k + 3];
            #pragma unroll
            for (int i = 0; i < 8; i++) {
                float4 a4 = *(const float4*)&sA[b0 + i][k];
                acc[i] += w0 * a4.x + w1 * a4.y + w2 * a4.z + w3 * a4.w;
            }
        }
        __syncthreads();
    }

    #pragma unroll
    for (int i = 0; i < 8; i++)
        outp[(size_t)(b0 + i) * G4 + r] = acc[i];
}

// ---------------- fused cell: combine partials + bias + onehot gather + LSTM gates ----------------
// grid 64 (b), 512 threads (d). mode 0 updates (h1,c1) w/ onehot; mode 1 updates (h2,c2).
__global__ void __launch_bounds__(512) cell_kernel(int mode, int step,
                                                   const int* __restrict__ x,
                                                   const float* __restrict__ Wih0)
{
    const int b = blockIdx.x, d = threadIdx.x;
    const size_t base = (size_t)b * G4;
    const float* bs = (mode == 0) ? g_bs0 : g_bs1;

    float gi = g_gp[0][base + d]        + g_gp[1][base + d]        + bs[d];
    float gf = g_gp[0][base + d + 512]  + g_gp[1][base + d + 512]  + bs[d + 512];
    float gg = g_gp[0][base + d + 1024] + g_gp[1][base + d + 1024] + bs[d + 1024];
    float go = g_gp[0][base + d + 1536] + g_gp[1][base + d + 1536] + bs[d + 1536];

    if (mode == 0) {
        int col = x[b * NN + step];
        gi += Wih0[(size_t)(d)        * 576 + col];
        gf += Wih0[(size_t)(d + 512)  * 576 + col];
        gg += Wih0[(size_t)(d + 1024) * 576 + col];
        go += Wih0[(size_t)(d + 1536) * 576 + col];
    }

    float* cbuf = (mode == 0) ? g_c1 : g_c2;
    float* hbuf = (mode == 0) ? g_h1 : g_h2;
    int idx = b * SS + d;
    float c = cbuf[idx];
    float cn = sigf(gf) * c + sigf(gi) * tanhf(gg);
    cbuf[idx] = cn;
    hbuf[idx] = sigf(go) * tanhf(cn);
}

// ---------------- fused attention + projection ----------------
// grid 64 (b), 512 threads. phi -> e -> softmax -> ctx -> p.
__global__ void __launch_bounds__(512) attn_kernel(const float* __restrict__ h,
                                                   const float* __restrict__ Wphi,
                                                   const float* __restrict__ bphi,
                                                   const float* __restrict__ Wcd,
                                                   const float* __restrict__ bcd,
                                                   float* __restrict__ out, int step)
{
    __shared__ __align__(16) float s_h2[SS];
    __shared__ __align__(16) float s_ctx[SS];
    __shared__ float s_phi[AT];
    __shared__ float s_alpha[TT];
    __shared__ float s_red[32];

    const int b = blockIdx.x, tid = threadIdx.x;
    const int lane = tid & 31, wid = tid >> 5;

    s_h2[tid] = g_h2[b * SS + tid];
    __syncthreads();

    // phi_s[a] = h2[b,:] . Wphi[a,:] + bphi[a]
    if (tid < AT) {
        const float4* wr = (const float4*)(Wphi + (size_t)tid * SS);
        const float4* hh = (const float4*)s_h2;
        float a = 0.f;
        #pragma unroll 4
        for (int k = 0; k < 128; k++) {
            float4 w = wr[k], v = hh[k];
            a += w.x * v.x + w.y * v.y + w.z * v.z + w.w * v.w;
        }
        s_phi[tid] = a + bphi[tid];
    }
    __syncthreads();

    // e[t] = phi . psiT[b][:][t]   (coalesced over t = tid)
    const float* prow = g_psiT + (size_t)b * AT * TT + tid;
    float e = 0.f;
    #pragma unroll 8
    for (int a = 0; a < AT; a++) e += s_phi[a] * prow[(size_t)a * TT];

    // block softmax over t (512)
    float m = e;
    #pragma unroll
    for (int off = 16; off; off >>= 1) m = fmaxf(m, __shfl_xor_sync(0xffffffffu, m, off));
    if (lane == 0) s_red[wid] = m;
    __syncthreads();
    if (wid == 0) {
        float v = (lane < 16) ? s_red[lane] : -1e30f;
        #pragma unroll
        for (int off = 8; off; off >>= 1) v = fmaxf(v, __shfl_xor_sync(0xffffffffu, v, off));
        if (lane == 0) s_red[0] = v;
    }
    __syncthreads();
    float M = s_red[0];
    float ex = expf(e - M);
    __syncthreads();
    float ssum = ex;
    #pragma unroll
    for (int off = 16; off; off >>= 1) ssum += __shfl_xor_sync(0xffffffffu, ssum, off);
    if (lane == 0) s_red[wid] = ssum;
    __syncthreads();
    if (wid == 0) {
        float v = (lane < 16) ? s_red[lane] : 0.f;
        #pragma unroll
        for (int off = 8; off; off >>= 1) v += __shfl_xor_sync(0xffffffffu, v, off);
        if (lane == 0) s_red[0] = v;
    }
    __syncthreads();
    s_alpha[tid] = ex / s_red[0];
    __syncthreads();

    // ctx[d] = sum_t alpha[t] * h[b,t,d]   (coalesced over d = tid)
    const float* hb = h + (size_t)b * TT * SS + tid;
    float acc = 0.f;
    #pragma unroll 8
    for (int t = 0; t < TT; t++) acc += s_alpha[t] * hb[(size_t)t * SS];
    s_ctx[tid] = acc;
    g_ctx[b * SS + tid] = acc;
    __syncthreads();

    // p[c] = concat(h2, ctx) . Wcd[c,:] + bcd[c]; 4 partial threads per class
    if (tid < 256) {
        int c = tid >> 2, part = tid & 3;
        const float4* wv = (const float4*)(Wcd + (size_t)c * 1024) + part * 64;
        const float4* src = (part < 2) ? ((const float4*)s_h2 + (part & 1) * 64)
                                       : ((const float4*)s_ctx + (part & 1) * 64);
        float p = 0.f;
        #pragma unroll 4
        for (int j = 0; j < 64; j++) {
            float4 w = wv[j], v = src[j];
            p += w.x * v.x + w.y * v.y + w.z * v.z + w.w * v.w;
        }
        p += __shfl_xor_sync(0xffffffffu, p, 1);
        p += __shfl_xor_sync(0xffffffffu, p, 2);
        if (part == 0)
            out[((size_t)b * NN + step) * NC + c] = p + bcd[c];
    }
}

// ---------------- host launcher ----------------
extern "C" void kernel_launch(void* const* d_in, const int* in_sizes, int n_in,
                              void* d_out, int out_size)
{
    const int*   x    = (const int*)  d_in[0];
    const float* h    = (const float*)d_in[1];
    const float* Wih0 = (const float*)d_in[2];
    const float* Whh0 = (const float*)d_in[3];
    const float* bih0 = (const float*)d_in[4];
    const float* bhh0 = (const float*)d_in[5];
    const float* Wih1 = (const float*)d_in[6];
    const float* Whh1 = (const float*)d_in[7];
    const float* bih1 = (const float*)d_in[8];
    const float* bhh1 = (const float*)d_in[9];
    const float* Wphi = (const float*)d_in[10];
    const float* bphi = (const float*)d_in[11];
    const float* Wpsi = (const float*)d_in[12];
    const float* bpsi = (const float*)d_in[13];
    const float* Wcd  = (const float*)d_in[14];
    const float* bcd  = (const float*)d_in[15];
    float* out = (float*)d_out;

    init_kernel<<<128, 256>>>(h, bih0, bhh0, bih1, bhh1);
    psi_kernel<<<(BB * TT) / 16, 128>>>(h, Wpsi, bpsi);

    dim3 ggrid(G4 / 32, 2);
    for (int s = 0; s < NN; s++) {
        gemm_kernel<<<ggrid, 256>>>(0, Wih0, 576, 64, Whh0);
        cell_kernel<<<BB, 512>>>(0, s, x, Wih0);
        gemm_kernel<<<ggrid, 256>>>(1, Wih1, 512, 0, Whh1);
        cell_kernel<<<BB, 512>>>(1, s, x, Wih0);
        attn_kernel<<<BB, 512>>>(h, Wphi, bphi, Wcd, bcd, out, s);
    }
}